// round 1
// baseline (speedup 1.0000x reference)
#include <cuda_runtime.h>

// ---------------------------------------------------------------------------
// Problem constants (from reference): B=16, T=32, NP=8, NG=4, J=14, H=256
//   BT = 512, heatmap elems = 16*32*256*256 = 33554432, J*3 = 42
//   perms = 8*7*6*5 = 1680 (lexicographic k-permutations of 8 choose 4)
// ---------------------------------------------------------------------------
#define BT        512
#define NP        8
#define NG        4
#define JD        42          // J*3
#define NPERM     1680
#define HM_ELEMS  33554432
#define HM_F4     (HM_ELEMS / 4)

// accumulators: 0=center sumsq, 1=offset sum, 2=size sum, 3=pose sum
__device__ double g_acc[4];

__global__ void zero_acc_kernel() {
    if (threadIdx.x < 4) g_acc[threadIdx.x] = 0.0;
}

// ---------------------------------------------------------------------------
// Heatmap MSE: sum((pred - gt)^2) over 33.5M elems. Memory-bound streaming.
// ---------------------------------------------------------------------------
__global__ void heatmap_mse_kernel(const float4* __restrict__ pred,
                                   const float4* __restrict__ gt) {
    float s = 0.0f;
    const int stride = gridDim.x * blockDim.x;
    for (int i = blockIdx.x * blockDim.x + threadIdx.x; i < HM_F4; i += stride) {
        float4 a = __ldg(&pred[i]);
        float4 b = __ldg(&gt[i]);
        float dx = a.x - b.x, dy = a.y - b.y, dz = a.z - b.z, dw = a.w - b.w;
        s += dx * dx + dy * dy + dz * dz + dw * dw;
    }
    // warp reduce
    #pragma unroll
    for (int off = 16; off > 0; off >>= 1)
        s += __shfl_down_sync(0xFFFFFFFFu, s, off);
    __shared__ float ws[8];
    int lane = threadIdx.x & 31, wid = threadIdx.x >> 5;
    if (lane == 0) ws[wid] = s;
    __syncthreads();
    if (wid == 0) {
        float v = (lane < (blockDim.x >> 5)) ? ws[lane] : 0.0f;
        #pragma unroll
        for (int off = 4; off > 0; off >>= 1)
            v += __shfl_down_sync(0xFFFFFFFFu, v, off);
        if (lane == 0) atomicAdd(&g_acc[0], (double)v);
    }
}

// ---------------------------------------------------------------------------
// Hungarian matching per (b,t). One CTA per bt, 256 threads.
// Exact enumeration of 1680 lexicographic perms (matches itertools order, so
// the u64-key atomicMin tie-break reproduces jnp.argmin first-min semantics).
// ---------------------------------------------------------------------------
__device__ __forceinline__ unsigned int fkey(float f) {
    unsigned int u = __float_as_uint(f);
    return (u & 0x80000000u) ? ~u : (u | 0x80000000u);   // monotone order-preserving
}

__device__ __forceinline__ void decode_perm(int p, int r[4]) {
    int avail[8] = {0, 1, 2, 3, 4, 5, 6, 7};
    const int div[4] = {210, 30, 5, 1};
    int n = 8;
    #pragma unroll
    for (int k = 0; k < 4; k++) {
        int idx = p / div[k];
        p -= idx * div[k];
        r[k] = avail[idx];
        for (int m = idx; m < n - 1; m++) avail[m] = avail[m + 1];
        n--;
    }
}

__global__ void match_kernel(const float* __restrict__ hor_offset,   // [BT,8,2]
                             const float* __restrict__ hor_bsize,    // [BT,8,4]
                             const float* __restrict__ hor_center,   // [BT,8,2]
                             const float* __restrict__ scores,       // [BT,8]
                             const float* __restrict__ x_pose3d,     // [BT,8,42]
                             const float* __restrict__ gt_wh,        // [BT,4,4]
                             const float* __restrict__ gt_off,       // [BT,4,2]
                             const float* __restrict__ gt_center,    // [BT,4,2]
                             const float* __restrict__ gt_pose)      // [BT,4,42]
{
    const int bt  = blockIdx.x;
    const int tid = threadIdx.x;

    __shared__ float pc[NP * 2], gc[NG * 2], sc[NP];
    __shared__ float po[NP * 2], go[NG * 2];
    __shared__ float ps[NP * 4], gs[NG * 4];
    __shared__ float pp[NP * JD], gp[NG * JD];
    __shared__ float Cb[NP][NG], Cp[NP][NG];
    __shared__ unsigned long long bestBox, bestPose;

    // cooperative loads
    for (int k = tid; k < NP * 2; k += blockDim.x) pc[k] = hor_center[bt * NP * 2 + k];
    for (int k = tid; k < NG * 2; k += blockDim.x) gc[k] = gt_center[bt * NG * 2 + k];
    for (int k = tid; k < NP;     k += blockDim.x) sc[k] = scores[bt * NP + k];
    for (int k = tid; k < NP * 2; k += blockDim.x) po[k] = hor_offset[bt * NP * 2 + k];
    for (int k = tid; k < NG * 2; k += blockDim.x) go[k] = gt_off[bt * NG * 2 + k];
    for (int k = tid; k < NP * 4; k += blockDim.x) ps[k] = hor_bsize[bt * NP * 4 + k];
    for (int k = tid; k < NG * 4; k += blockDim.x) gs[k] = gt_wh[bt * NG * 4 + k];
    for (int k = tid; k < NP * JD; k += blockDim.x) pp[k] = x_pose3d[bt * NP * JD + k];
    for (int k = tid; k < NG * JD; k += blockDim.x) gp[k] = gt_pose[bt * NG * JD + k];
    if (tid == 0) { bestBox = ~0ULL; bestPose = ~0ULL; }
    __syncthreads();

    // cost matrices (32 entries each)
    if (tid < NP * NG) {
        int i = tid >> 2, j = tid & 3;
        float dx = pc[i * 2 + 0] - gc[j * 2 + 0];
        float dy = pc[i * 2 + 1] - gc[j * 2 + 1];
        Cb[i][j] = sqrtf(dx * dx + dy * dy) - sc[i];
        float acc = 0.0f;
        for (int k = 0; k < JD; k++) {
            float d = pp[i * JD + k] - gp[j * JD + k];
            acc += d * d;
        }
        Cp[i][j] = sqrtf(acc);
    }
    __syncthreads();

    // enumerate perms
    unsigned long long lb = ~0ULL, lp = ~0ULL;
    for (int p = tid; p < NPERM; p += blockDim.x) {
        int r[4];
        decode_perm(p, r);
        float cb = Cb[r[0]][0] + Cb[r[1]][1] + Cb[r[2]][2] + Cb[r[3]][3];
        float cp = Cp[r[0]][0] + Cp[r[1]][1] + Cp[r[2]][2] + Cp[r[3]][3];
        unsigned long long kb = ((unsigned long long)fkey(cb) << 32) | (unsigned)p;
        unsigned long long kp = ((unsigned long long)fkey(cp) << 32) | (unsigned)p;
        lb = min(lb, kb);
        lp = min(lp, kp);
    }
    atomicMin(&bestBox, lb);
    atomicMin(&bestPose, lp);
    __syncthreads();

    if (tid == 0) {
        int r[4];
        decode_perm((int)(bestBox & 0xFFFFFFFFu), r);
        float off = 0.0f, sz = 0.0f;
        #pragma unroll
        for (int j = 0; j < NG; j++) {
            int i = r[j];
            off += 0.5f * (fabsf(po[i * 2 + 0] - go[j * 2 + 0]) +
                           fabsf(po[i * 2 + 1] - go[j * 2 + 1]));
            float s4 = 0.0f;
            #pragma unroll
            for (int k = 0; k < 4; k++) s4 += fabsf(ps[i * 4 + k] - gs[j * 4 + k]);
            sz += 0.25f * s4;
        }
        atomicAdd(&g_acc[1], (double)off);
        atomicAdd(&g_acc[2], (double)sz);
    }
    if (tid == 1) {
        int r[4];
        decode_perm((int)(bestPose & 0xFFFFFFFFu), r);
        float s = 0.0f;
        #pragma unroll
        for (int j = 0; j < NG; j++) {
            int i = r[j];
            for (int k = 0; k < JD; k++) {
                float d = pp[i * JD + k] - gp[j * JD + k];
                s += d * d;
            }
        }
        atomicAdd(&g_acc[3], (double)s);
    }
}

// ---------------------------------------------------------------------------
// Finalize: combine into scalar output.
// loss = mean(center) + off/BT + size/BT + pose/(BT*NP*J)
// ---------------------------------------------------------------------------
__global__ void finalize_kernel(float* __restrict__ out) {
    double center = g_acc[0] / (double)HM_ELEMS;
    double off    = g_acc[1] / (double)BT;
    double sz     = g_acc[2] / (double)BT;
    double pose   = g_acc[3] / (double)(BT * NP * 14);
    out[0] = (float)(center + off + sz + pose);
}

extern "C" void kernel_launch(void* const* d_in, const int* in_sizes, int n_in,
                              void* d_out, int out_size) {
    const float* hor_heatmap = (const float*)d_in[0];
    const float* hor_offset  = (const float*)d_in[1];
    const float* hor_bsize   = (const float*)d_in[2];
    const float* hor_center  = (const float*)d_in[3];
    const float* scores      = (const float*)d_in[4];
    const float* x_pose3d    = (const float*)d_in[5];
    const float* gt_heatmap  = (const float*)d_in[6];
    const float* gt_wh       = (const float*)d_in[7];
    const float* gt_off      = (const float*)d_in[8];
    const float* gt_center   = (const float*)d_in[9];
    const float* gt_pose     = (const float*)d_in[10];
    float* out = (float*)d_out;

    zero_acc_kernel<<<1, 32>>>();
    heatmap_mse_kernel<<<2048, 256>>>((const float4*)hor_heatmap,
                                      (const float4*)gt_heatmap);
    match_kernel<<<BT, 256>>>(hor_offset, hor_bsize, hor_center, scores, x_pose3d,
                              gt_wh, gt_off, gt_center, gt_pose);
    finalize_kernel<<<1, 1>>>(out);
}